// round 1
// baseline (speedup 1.0000x reference)
#include <cuda_runtime.h>
#include <cuda_bf16.h>
#include <math.h>

// ContextVAE fused kernel, fp32 scalar path.
// One thread == one batch element. Weights pre-packed into shared memory
// with one-hot features folded into biases.

#define BATCH 262144
#define NTHREADS 256

// Shared layout (floats):
//  sW1w  [128*4]  : {W1[o,10], W1[o,11], W1[o,12], 0}
//  sB1e  [4*128]  : b1[o] + W1[o,0] + W1[o,6+e]
//  sW2T  [128*40] : row k: W2[j,k] for j<39, pad 0
//  sW3   [128*40] : row j: W3[j,k] for k<39, [39] = b3[j]
//  sWmv  [128*16] : row j: {Wm[0..7, j], Wv[0..7, j]}
//  sWd1  [32*24]  : row h: {Wd1[h,5..16], Wd1[h,17..24], bd1[h]+Wd1[h,0], 0,0,0}
//  sWd2  [32*16]  : row h: {Wd2[0..11, h], pad}
//  sBmv  [16]     : {bm[0..7], bv[0..7]}
//  sBd2  [16]     : bd2[0..11]
//  sB2   [40]     : b2[0..38], pad 0
#define OFF_W1W  0
#define OFF_B1E  (OFF_W1W + 128*4)
#define OFF_W2T  (OFF_B1E + 4*128)
#define OFF_W3   (OFF_W2T + 128*40)
#define OFF_WMV  (OFF_W3  + 128*40)
#define OFF_WD1  (OFF_WMV + 128*16)
#define OFF_WD2  (OFF_WD1 + 32*24)
#define OFF_BMV  (OFF_WD2 + 32*16)
#define OFF_BD2  (OFF_BMV + 16)
#define OFF_B2   (OFF_BD2 + 16)
#define SMEM_FLOATS (OFF_B2 + 40)
#define SMEM_BYTES  (SMEM_FLOATS * 4)

__global__ __launch_bounds__(NTHREADS, 1)
void vae_kernel(const float* __restrict__ initial_c,
                const float* __restrict__ current_c,
                const float* __restrict__ eps,
                const float* __restrict__ W1, const float* __restrict__ b1,
                const float* __restrict__ W2, const float* __restrict__ b2,
                const float* __restrict__ W3, const float* __restrict__ b3,
                const float* __restrict__ Wm, const float* __restrict__ bm,
                const float* __restrict__ Wv, const float* __restrict__ bv,
                const float* __restrict__ Wd1, const float* __restrict__ bd1,
                const float* __restrict__ Wd2, const float* __restrict__ bd2,
                float* __restrict__ out)
{
    extern __shared__ float sm[];
    float* sW1w = sm + OFF_W1W;
    float* sB1e = sm + OFF_B1E;
    float* sW2T = sm + OFF_W2T;
    float* sW3  = sm + OFF_W3;
    float* sWmv = sm + OFF_WMV;
    float* sWd1 = sm + OFF_WD1;
    float* sWd2 = sm + OFF_WD2;
    float* sBmv = sm + OFF_BMV;
    float* sBd2 = sm + OFF_BD2;
    float* sB2  = sm + OFF_B2;

    const int t = threadIdx.x;

    // ---- pack weights into shared ----
    for (int o = t; o < 128; o += NTHREADS) {
        float w0 = __ldg(&W1[o*13 + 0]);
        sW1w[o*4 + 0] = __ldg(&W1[o*13 + 10]);
        sW1w[o*4 + 1] = __ldg(&W1[o*13 + 11]);
        sW1w[o*4 + 2] = __ldg(&W1[o*13 + 12]);
        sW1w[o*4 + 3] = 0.f;
        float bb = __ldg(&b1[o]) + w0;
        #pragma unroll
        for (int e = 0; e < 4; e++)
            sB1e[e*128 + o] = bb + __ldg(&W1[o*13 + 6 + e]);
    }
    for (int i = t; i < 128*40; i += NTHREADS) {
        int k = i / 40, j = i % 40;
        sW2T[i] = (j < 39) ? __ldg(&W2[j*128 + k]) : 0.f;
    }
    for (int i = t; i < 128*40; i += NTHREADS) {
        int j = i / 40, k = i % 40;
        sW3[i] = (k < 39) ? __ldg(&W3[j*39 + k]) : __ldg(&b3[j]);
    }
    for (int i = t; i < 128*16; i += NTHREADS) {
        int j = i / 16, q = i % 16;
        sWmv[i] = (q < 8) ? __ldg(&Wm[q*128 + j]) : __ldg(&Wv[(q-8)*128 + j]);
    }
    for (int i = t; i < 32*24; i += NTHREADS) {
        int h = i / 24, q = i % 24;
        float v;
        if (q < 12)       v = __ldg(&Wd1[h*25 + 5 + q]);
        else if (q < 20)  v = __ldg(&Wd1[h*25 + 17 + (q-12)]);
        else if (q == 20) v = __ldg(&bd1[h]) + __ldg(&Wd1[h*25 + 0]);
        else              v = 0.f;
        sWd1[i] = v;
    }
    for (int i = t; i < 32*16; i += NTHREADS) {
        int h = i / 16, j = i % 16;
        sWd2[i] = (j < 12) ? __ldg(&Wd2[j*32 + h]) : 0.f;
    }
    if (t < 16) sBmv[t] = (t < 8) ? __ldg(&bm[t]) : __ldg(&bv[t-8]);
    if (t < 16) sBd2[t] = (t < 12) ? __ldg(&bd2[t]) : 0.f;
    if (t < 40) sB2[t]  = (t < 39) ? __ldg(&b2[t]) : 0.f;
    __syncthreads();

    const int b = blockIdx.x * NTHREADS + t;

    // ---- gather current_c values: indices {0..3, 10..13, 14, 18, 22, 26} ----
    const float* cc = current_c + (size_t)b * 30;
    float cur[12];
    cur[0]  = __ldg(&cc[0]);  cur[1]  = __ldg(&cc[1]);
    cur[2]  = __ldg(&cc[2]);  cur[3]  = __ldg(&cc[3]);
    cur[4]  = __ldg(&cc[10]); cur[5]  = __ldg(&cc[11]);
    cur[6]  = __ldg(&cc[12]); cur[7]  = __ldg(&cc[13]);
    cur[8]  = __ldg(&cc[14]); cur[9]  = __ldg(&cc[18]);
    cur[10] = __ldg(&cc[22]); cur[11] = __ldg(&cc[26]);

    // ---- message stage: 4 edges, 13->128->39 (relu), summed ----
    float msum[40];
    #pragma unroll
    for (int j = 0; j < 40; j++) msum[j] = 0.f;

    #pragma unroll
    for (int e = 0; e < 4; e++) {
        const float p0 = cur[e], p1 = cur[4+e], p2 = cur[8+e];
        const float* b1e = sB1e + e*128;
        float acc[40];
        #pragma unroll
        for (int j = 0; j < 40; j++) acc[j] = sB2[j];

        #pragma unroll 4
        for (int k = 0; k < 128; k++) {
            float4 w = ((const float4*)sW1w)[k];
            float x1 = fmaf(w.x, p0, fmaf(w.y, p1, fmaf(w.z, p2, b1e[k])));
            x1 = fmaxf(x1, 0.f);
            const float4* w2 = (const float4*)(sW2T + k*40);
            #pragma unroll
            for (int jj = 0; jj < 10; jj++) {
                float4 c = w2[jj];
                acc[jj*4+0] = fmaf(c.x, x1, acc[jj*4+0]);
                acc[jj*4+1] = fmaf(c.y, x1, acc[jj*4+1]);
                acc[jj*4+2] = fmaf(c.z, x1, acc[jj*4+2]);
                acc[jj*4+3] = fmaf(c.w, x1, acc[jj*4+3]);
            }
        }
        #pragma unroll
        for (int j = 0; j < 40; j++) msum[j] += fmaxf(acc[j], 0.f);
    }

    // ---- readout: 39 -> 128 (relu) -> means/log_var (8+8) ----
    msum[39] = 1.f;   // bias trick: sW3 row's element 39 holds b3[j]
    float mv[16];
    #pragma unroll
    for (int i = 0; i < 16; i++) mv[i] = sBmv[i];

    #pragma unroll 2
    for (int j = 0; j < 128; j++) {
        const float4* w3 = (const float4*)(sW3 + j*40);
        float s0 = 0.f, s1 = 0.f, s2 = 0.f, s3 = 0.f;
        #pragma unroll
        for (int kk = 0; kk < 10; kk++) {
            float4 c = w3[kk];
            s0 = fmaf(c.x, msum[kk*4+0], s0);
            s1 = fmaf(c.y, msum[kk*4+1], s1);
            s2 = fmaf(c.z, msum[kk*4+2], s2);
            s3 = fmaf(c.w, msum[kk*4+3], s3);
        }
        float x3 = fmaxf((s0 + s1) + (s2 + s3), 0.f);
        const float4* wmv = (const float4*)(sWmv + j*16);
        #pragma unroll
        for (int ii = 0; ii < 4; ii++) {
            float4 c = wmv[ii];
            mv[ii*4+0] = fmaf(c.x, x3, mv[ii*4+0]);
            mv[ii*4+1] = fmaf(c.y, x3, mv[ii*4+1]);
            mv[ii*4+2] = fmaf(c.z, x3, mv[ii*4+2]);
            mv[ii*4+3] = fmaf(c.w, x3, mv[ii*4+3]);
        }
    }

    // ---- reparameterization ----
    const float4* ep = (const float4*)(eps + (size_t)b * 8);
    float4 e0 = ep[0], e1 = ep[1];
    float epsv[8] = {e0.x, e0.y, e0.z, e0.w, e1.x, e1.y, e1.z, e1.w};
    float zv[8];
    #pragma unroll
    for (int i = 0; i < 8; i++)
        zv[i] = fmaf(epsv[i], expf(0.5f * mv[8+i]), mv[i]);

    // ---- decoder: [initial_c[o_ids] | z | 1] (21 used, padded 24) -> 32 relu -> 12 sigmoid ----
    const float* ic = initial_c + (size_t)b * 30;
    float d[24];
    d[0]  = __ldg(&ic[0]);  d[1]  = __ldg(&ic[1]);
    d[2]  = __ldg(&ic[2]);  d[3]  = __ldg(&ic[3]);
    d[4]  = __ldg(&ic[10]); d[5]  = __ldg(&ic[11]);
    d[6]  = __ldg(&ic[12]); d[7]  = __ldg(&ic[13]);
    d[8]  = __ldg(&ic[14]); d[9]  = __ldg(&ic[18]);
    d[10] = __ldg(&ic[22]); d[11] = __ldg(&ic[26]);
    #pragma unroll
    for (int i = 0; i < 8; i++) d[12+i] = zv[i];
    d[20] = 1.f; d[21] = 0.f; d[22] = 0.f; d[23] = 0.f;

    float r[12];
    #pragma unroll
    for (int j = 0; j < 12; j++) r[j] = sBd2[j];

    #pragma unroll 4
    for (int h = 0; h < 32; h++) {
        const float4* w1 = (const float4*)(sWd1 + h*24);
        float s0 = 0.f, s1 = 0.f, s2 = 0.f, s3 = 0.f;
        #pragma unroll
        for (int q = 0; q < 6; q++) {
            float4 c = w1[q];
            s0 = fmaf(c.x, d[q*4+0], s0);
            s1 = fmaf(c.y, d[q*4+1], s1);
            s2 = fmaf(c.z, d[q*4+2], s2);
            s3 = fmaf(c.w, d[q*4+3], s3);
        }
        float hv = fmaxf((s0 + s1) + (s2 + s3), 0.f);
        const float4* w2 = (const float4*)(sWd2 + h*16);
        #pragma unroll
        for (int ii = 0; ii < 3; ii++) {
            float4 c = w2[ii];
            r[ii*4+0] = fmaf(c.x, hv, r[ii*4+0]);
            r[ii*4+1] = fmaf(c.y, hv, r[ii*4+1]);
            r[ii*4+2] = fmaf(c.z, hv, r[ii*4+2]);
            r[ii*4+3] = fmaf(c.w, hv, r[ii*4+3]);
        }
    }

    // ---- stores: recon_x [B,12] | means [B,8] | log_var [B,8] | z [B,8] ----
    float* out_rec = out + (size_t)b * 12;
    #pragma unroll
    for (int ii = 0; ii < 3; ii++) {
        float4 v;
        v.x = 1.f / (1.f + expf(-r[ii*4+0]));
        v.y = 1.f / (1.f + expf(-r[ii*4+1]));
        v.z = 1.f / (1.f + expf(-r[ii*4+2]));
        v.w = 1.f / (1.f + expf(-r[ii*4+3]));
        ((float4*)out_rec)[ii] = v;
    }
    float* out_mean = out + (size_t)12*BATCH + (size_t)b*8;
    ((float4*)out_mean)[0] = make_float4(mv[0], mv[1], mv[2], mv[3]);
    ((float4*)out_mean)[1] = make_float4(mv[4], mv[5], mv[6], mv[7]);
    float* out_lv = out + (size_t)20*BATCH + (size_t)b*8;
    ((float4*)out_lv)[0] = make_float4(mv[8],  mv[9],  mv[10], mv[11]);
    ((float4*)out_lv)[1] = make_float4(mv[12], mv[13], mv[14], mv[15]);
    float* out_z = out + (size_t)28*BATCH + (size_t)b*8;
    ((float4*)out_z)[0] = make_float4(zv[0], zv[1], zv[2], zv[3]);
    ((float4*)out_z)[1] = make_float4(zv[4], zv[5], zv[6], zv[7]);
}

extern "C" void kernel_launch(void* const* d_in, const int* in_sizes, int n_in,
                              void* d_out, int out_size)
{
    const float* initial_c = (const float*)d_in[0];
    // d_in[1] = initial_s (unused by the reference computation)
    const float* current_c = (const float*)d_in[2];
    const float* eps       = (const float*)d_in[3];
    const float* W1  = (const float*)d_in[4];
    const float* b1  = (const float*)d_in[5];
    const float* W2  = (const float*)d_in[6];
    const float* b2  = (const float*)d_in[7];
    const float* W3  = (const float*)d_in[8];
    const float* b3  = (const float*)d_in[9];
    const float* Wm  = (const float*)d_in[10];
    const float* bm  = (const float*)d_in[11];
    const float* Wv  = (const float*)d_in[12];
    const float* bv  = (const float*)d_in[13];
    const float* Wd1 = (const float*)d_in[14];
    const float* bd1 = (const float*)d_in[15];
    const float* Wd2 = (const float*)d_in[16];
    const float* bd2 = (const float*)d_in[17];
    float* out = (float*)d_out;

    cudaFuncSetAttribute(vae_kernel, cudaFuncAttributeMaxDynamicSharedMemorySize, SMEM_BYTES);
    vae_kernel<<<BATCH / NTHREADS, NTHREADS, SMEM_BYTES>>>(
        initial_c, current_c, eps,
        W1, b1, W2, b2, W3, b3, Wm, bm, Wv, bv, Wd1, bd1, Wd2, bd2,
        out);
}

// round 2
// speedup vs baseline: 1.2880x; 1.2880x over previous
#include <cuda_runtime.h>
#include <cuda_bf16.h>
#include <math.h>

// ContextVAE fused kernel, fp32 with packed f32x2 (FFMA2) math + edge-pairing.
// One thread == one batch element. Weights pre-packed into shared memory.

#define BATCH 262144
#define NTHREADS 256

typedef unsigned long long u64;

__device__ __forceinline__ u64 f2fma(u64 a, u64 b, u64 c) {
    u64 d;
    asm("fma.rn.f32x2 %0, %1, %2, %3;" : "=l"(d) : "l"(a), "l"(b), "l"(c));
    return d;
}
__device__ __forceinline__ u64 f2add(u64 a, u64 b) {
    u64 d;
    asm("add.rn.f32x2 %0, %1, %2;" : "=l"(d) : "l"(a), "l"(b));
    return d;
}
__device__ __forceinline__ u64 f2pack(float lo, float hi) {
    u64 r;
    asm("mov.b64 %0, {%1, %2};" : "=l"(r) : "f"(lo), "f"(hi));
    return r;
}
__device__ __forceinline__ u64 f2dup(float v) {
    u64 r;
    asm("mov.b64 %0, {%1, %1};" : "=l"(r) : "f"(v));
    return r;
}
__device__ __forceinline__ float2 f2unpack(u64 p) {
    float2 r;
    asm("mov.b64 {%0, %1}, %2;" : "=f"(r.x), "=f"(r.y) : "l"(p));
    return r;
}

// Shared layout (floats), all offsets 16B-aligned:
//  sW1e  [4*128*4] : per edge e, per neuron o: {W1[o,10], W1[o,11], W1[o,12], b1[o]+W1[o,0]+W1[o,6+e]}
//  sW2T  [128*40]  : row k: W2[j,k] for j<39, pad 0
//  sW3   [128*40]  : row j: W3[j,k] for k<39, [39] = b3[j]
//  sWmv  [128*16]  : row j: {Wm[0..7, j], Wv[0..7, j]}
//  sWd1  [32*24]   : row h: {Wd1[h,5..16], Wd1[h,17..24], bd1[h]+Wd1[h,0], 0,0,0}
//  sWd2  [32*12]   : row h: Wd2[0..11, h]
//  sBmv  [16], sBd2 [12], sB2 [40]
#define OFF_W1E  0
#define OFF_W2T  (OFF_W1E + 4*128*4)
#define OFF_W3   (OFF_W2T + 128*40)
#define OFF_WMV  (OFF_W3  + 128*40)
#define OFF_WD1  (OFF_WMV + 128*16)
#define OFF_WD2  (OFF_WD1 + 32*24)
#define OFF_BMV  (OFF_WD2 + 32*12)
#define OFF_BD2  (OFF_BMV + 16)
#define OFF_B2   (OFF_BD2 + 12)
#define SMEM_FLOATS (OFF_B2 + 40)
#define SMEM_BYTES  (SMEM_FLOATS * 4)

__global__ __launch_bounds__(NTHREADS, 1)
void vae_kernel(const float* __restrict__ initial_c,
                const float* __restrict__ current_c,
                const float* __restrict__ eps,
                const float* __restrict__ W1, const float* __restrict__ b1,
                const float* __restrict__ W2, const float* __restrict__ b2,
                const float* __restrict__ W3, const float* __restrict__ b3,
                const float* __restrict__ Wm, const float* __restrict__ bm,
                const float* __restrict__ Wv, const float* __restrict__ bv,
                const float* __restrict__ Wd1, const float* __restrict__ bd1,
                const float* __restrict__ Wd2, const float* __restrict__ bd2,
                float* __restrict__ out)
{
    extern __shared__ float sm[];
    float* sW1e = sm + OFF_W1E;
    float* sW2T = sm + OFF_W2T;
    float* sW3  = sm + OFF_W3;
    float* sWmv = sm + OFF_WMV;
    float* sWd1 = sm + OFF_WD1;
    float* sWd2 = sm + OFF_WD2;
    float* sBmv = sm + OFF_BMV;
    float* sBd2 = sm + OFF_BD2;
    float* sB2  = sm + OFF_B2;

    const int t = threadIdx.x;

    // ---- pack weights into shared ----
    for (int i = t; i < 4*128; i += NTHREADS) {
        int e = i >> 7, o = i & 127;
        float4 v;
        v.x = __ldg(&W1[o*13 + 10]);
        v.y = __ldg(&W1[o*13 + 11]);
        v.z = __ldg(&W1[o*13 + 12]);
        v.w = __ldg(&b1[o]) + __ldg(&W1[o*13 + 0]) + __ldg(&W1[o*13 + 6 + e]);
        ((float4*)sW1e)[i] = v;
    }
    for (int i = t; i < 128*40; i += NTHREADS) {
        int k = i / 40, j = i % 40;
        sW2T[i] = (j < 39) ? __ldg(&W2[j*128 + k]) : 0.f;
    }
    for (int i = t; i < 128*40; i += NTHREADS) {
        int j = i / 40, k = i % 40;
        sW3[i] = (k < 39) ? __ldg(&W3[j*39 + k]) : __ldg(&b3[j]);
    }
    for (int i = t; i < 128*16; i += NTHREADS) {
        int j = i / 16, q = i % 16;
        sWmv[i] = (q < 8) ? __ldg(&Wm[q*128 + j]) : __ldg(&Wv[(q-8)*128 + j]);
    }
    for (int i = t; i < 32*24; i += NTHREADS) {
        int h = i / 24, q = i % 24;
        float v;
        if (q < 12)       v = __ldg(&Wd1[h*25 + 5 + q]);
        else if (q < 20)  v = __ldg(&Wd1[h*25 + 17 + (q-12)]);
        else if (q == 20) v = __ldg(&bd1[h]) + __ldg(&Wd1[h*25 + 0]);
        else              v = 0.f;
        sWd1[i] = v;
    }
    for (int i = t; i < 32*12; i += NTHREADS) {
        int h = i / 12, j = i % 12;
        sWd2[i] = __ldg(&Wd2[j*32 + h]);
    }
    if (t < 16) sBmv[t] = (t < 8) ? __ldg(&bm[t]) : __ldg(&bv[t-8]);
    if (t < 12) sBd2[t] = __ldg(&bd2[t]);
    if (t < 40) sB2[t]  = (t < 39) ? __ldg(&b2[t]) : 0.f;
    __syncthreads();

    const int b = blockIdx.x * NTHREADS + t;

    // ---- gather current_c: indices {0..3, 10..13, 14, 18, 22, 26} ----
    const float* cc = current_c + (size_t)b * 30;
    float cur[12];
    cur[0]  = __ldg(&cc[0]);  cur[1]  = __ldg(&cc[1]);
    cur[2]  = __ldg(&cc[2]);  cur[3]  = __ldg(&cc[3]);
    cur[4]  = __ldg(&cc[10]); cur[5]  = __ldg(&cc[11]);
    cur[6]  = __ldg(&cc[12]); cur[7]  = __ldg(&cc[13]);
    cur[8]  = __ldg(&cc[14]); cur[9]  = __ldg(&cc[18]);
    cur[10] = __ldg(&cc[22]); cur[11] = __ldg(&cc[26]);

    // ---- message stage: 4 edges (processed as 2 pairs), 13->128->39 relu, summed ----
    u64 msum2[20];
    #pragma unroll
    for (int q = 0; q < 20; q++) msum2[q] = 0ULL;

    #pragma unroll
    for (int ep = 0; ep < 2; ep++) {
        const int eA = 2*ep, eB = 2*ep + 1;
        const float pA0 = cur[eA], pA1 = cur[4+eA], pA2 = cur[8+eA];
        const float pB0 = cur[eB], pB1 = cur[4+eB], pB2 = cur[8+eB];
        const float4* w1A = (const float4*)(sW1e) + eA*128;
        const float4* w1B = (const float4*)(sW1e) + eB*128;

        u64 accA[20], accB[20];
        {
            const ulonglong2* bb = (const ulonglong2*)sB2;
            #pragma unroll
            for (int q = 0; q < 10; q++) {
                ulonglong2 v = bb[q];
                accA[2*q]   = v.x; accA[2*q+1] = v.y;
                accB[2*q]   = v.x; accB[2*q+1] = v.y;
            }
        }

        #pragma unroll 2
        for (int k = 0; k < 128; k++) {
            float4 wA = w1A[k];
            float4 wB = w1B[k];
            float x1a = fmaxf(fmaf(wA.x, pA0, fmaf(wA.y, pA1, fmaf(wA.z, pA2, wA.w))), 0.f);
            float x1b = fmaxf(fmaf(wB.x, pB0, fmaf(wB.y, pB1, fmaf(wB.z, pB2, wB.w))), 0.f);
            u64 xa = f2dup(x1a);
            u64 xb = f2dup(x1b);
            const ulonglong2* crow = (const ulonglong2*)(sW2T + k*40);
            #pragma unroll
            for (int q = 0; q < 10; q++) {
                ulonglong2 c = crow[q];
                accA[2*q]   = f2fma(c.x, xa, accA[2*q]);
                accA[2*q+1] = f2fma(c.y, xa, accA[2*q+1]);
                accB[2*q]   = f2fma(c.x, xb, accB[2*q]);
                accB[2*q+1] = f2fma(c.y, xb, accB[2*q+1]);
            }
        }

        // relu per edge, sum into msum
        #pragma unroll
        for (int q = 0; q < 20; q++) {
            float2 a = f2unpack(accA[q]);
            float2 c = f2unpack(accB[q]);
            float lo = fmaxf(a.x, 0.f) + fmaxf(c.x, 0.f);
            float hi = fmaxf(a.y, 0.f) + fmaxf(c.y, 0.f);
            msum2[q] = f2add(msum2[q], f2pack(lo, hi));
        }
    }

    // bias trick: element 39 of msum participates with W3 row's [39] = b3
    {
        float2 v = f2unpack(msum2[19]);
        msum2[19] = f2pack(v.x, 1.0f);
    }

    // ---- readout: 39(+1) -> 128 relu -> means/log_var (8+8) ----
    u64 mv2[8];
    {
        const ulonglong2* bb = (const ulonglong2*)sBmv;
        #pragma unroll
        for (int q = 0; q < 4; q++) {
            ulonglong2 v = bb[q];
            mv2[2*q] = v.x; mv2[2*q+1] = v.y;
        }
    }

    #pragma unroll 2
    for (int j = 0; j < 128; j++) {
        const ulonglong2* w3r = (const ulonglong2*)(sW3 + j*40);
        u64 s0 = 0ULL, s1 = 0ULL, s2 = 0ULL, s3 = 0ULL;
        #pragma unroll
        for (int q = 0; q < 10; q += 2) {
            ulonglong2 c0 = w3r[q];
            ulonglong2 c1 = w3r[q+1];
            s0 = f2fma(c0.x, msum2[2*q],   s0);
            s1 = f2fma(c0.y, msum2[2*q+1], s1);
            s2 = f2fma(c1.x, msum2[2*q+2], s2);
            s3 = f2fma(c1.y, msum2[2*q+3], s3);
        }
        u64 st = f2add(f2add(s0, s2), f2add(s1, s3));
        float2 u = f2unpack(st);
        float x3 = fmaxf(u.x + u.y, 0.f);
        u64 xp = f2dup(x3);
        const ulonglong2* wm = (const ulonglong2*)(sWmv + j*16);
        #pragma unroll
        for (int q = 0; q < 4; q++) {
            ulonglong2 c = wm[q];
            mv2[2*q]   = f2fma(c.x, xp, mv2[2*q]);
            mv2[2*q+1] = f2fma(c.y, xp, mv2[2*q+1]);
        }
    }

    // ---- reparameterization ----
    float mvs[16];
    #pragma unroll
    for (int q = 0; q < 8; q++) {
        float2 v = f2unpack(mv2[q]);
        mvs[2*q] = v.x; mvs[2*q+1] = v.y;
    }
    const float4* epv = (const float4*)(eps + (size_t)b * 8);
    float4 e0 = epv[0], e1 = epv[1];
    float epsv[8] = {e0.x, e0.y, e0.z, e0.w, e1.x, e1.y, e1.z, e1.w};
    float zv[8];
    #pragma unroll
    for (int i = 0; i < 8; i++)
        zv[i] = fmaf(epsv[i], expf(0.5f * mvs[8+i]), mvs[i]);

    // ---- decoder: [ic[o_ids] | z | 1 | pads] (24) -> 32 relu -> 12 sigmoid ----
    const float* ic = initial_c + (size_t)b * 30;
    u64 d2[12];
    d2[0] = f2pack(__ldg(&ic[0]),  __ldg(&ic[1]));
    d2[1] = f2pack(__ldg(&ic[2]),  __ldg(&ic[3]));
    d2[2] = f2pack(__ldg(&ic[10]), __ldg(&ic[11]));
    d2[3] = f2pack(__ldg(&ic[12]), __ldg(&ic[13]));
    d2[4] = f2pack(__ldg(&ic[14]), __ldg(&ic[18]));
    d2[5] = f2pack(__ldg(&ic[22]), __ldg(&ic[26]));
    d2[6] = f2pack(zv[0], zv[1]);
    d2[7] = f2pack(zv[2], zv[3]);
    d2[8] = f2pack(zv[4], zv[5]);
    d2[9] = f2pack(zv[6], zv[7]);
    d2[10] = f2pack(1.f, 0.f);
    d2[11] = 0ULL;

    u64 r2[6];
    {
        const ulonglong2* bb = (const ulonglong2*)sBd2;
        #pragma unroll
        for (int q = 0; q < 3; q++) {
            ulonglong2 v = bb[q];
            r2[2*q] = v.x; r2[2*q+1] = v.y;
        }
    }

    #pragma unroll 4
    for (int h = 0; h < 32; h++) {
        const ulonglong2* w1r = (const ulonglong2*)(sWd1 + h*24);
        u64 t0 = 0ULL, t1 = 0ULL, t2 = 0ULL, t3 = 0ULL;
        #pragma unroll
        for (int q = 0; q < 6; q += 2) {
            ulonglong2 c0 = w1r[q];
            ulonglong2 c1 = w1r[q+1];
            t0 = f2fma(c0.x, d2[2*q],   t0);
            t1 = f2fma(c0.y, d2[2*q+1], t1);
            t2 = f2fma(c1.x, d2[2*q+2], t2);
            t3 = f2fma(c1.y, d2[2*q+3], t3);
        }
        u64 st = f2add(f2add(t0, t2), f2add(t1, t3));
        float2 u = f2unpack(st);
        float hv = fmaxf(u.x + u.y, 0.f);
        u64 hp = f2dup(hv);
        const ulonglong2* w2r = (const ulonglong2*)(sWd2 + h*12);
        #pragma unroll
        for (int q = 0; q < 3; q++) {
            ulonglong2 c = w2r[q];
            r2[2*q]   = f2fma(c.x, hp, r2[2*q]);
            r2[2*q+1] = f2fma(c.y, hp, r2[2*q+1]);
        }
    }

    // ---- stores: recon_x [B,12] | means [B,8] | log_var [B,8] | z [B,8] ----
    float rr[12];
    #pragma unroll
    for (int q = 0; q < 6; q++) {
        float2 v = f2unpack(r2[q]);
        rr[2*q] = v.x; rr[2*q+1] = v.y;
    }
    float* out_rec = out + (size_t)b * 12;
    #pragma unroll
    for (int ii = 0; ii < 3; ii++) {
        float4 v;
        v.x = 1.f / (1.f + expf(-rr[ii*4+0]));
        v.y = 1.f / (1.f + expf(-rr[ii*4+1]));
        v.z = 1.f / (1.f + expf(-rr[ii*4+2]));
        v.w = 1.f / (1.f + expf(-rr[ii*4+3]));
        ((float4*)out_rec)[ii] = v;
    }
    float* out_mean = out + (size_t)12*BATCH + (size_t)b*8;
    ((float4*)out_mean)[0] = make_float4(mvs[0], mvs[1], mvs[2], mvs[3]);
    ((float4*)out_mean)[1] = make_float4(mvs[4], mvs[5], mvs[6], mvs[7]);
    float* out_lv = out + (size_t)20*BATCH + (size_t)b*8;
    ((float4*)out_lv)[0] = make_float4(mvs[8],  mvs[9],  mvs[10], mvs[11]);
    ((float4*)out_lv)[1] = make_float4(mvs[12], mvs[13], mvs[14], mvs[15]);
    float* out_z = out + (size_t)28*BATCH + (size_t)b*8;
    ((float4*)out_z)[0] = make_float4(zv[0], zv[1], zv[2], zv[3]);
    ((float4*)out_z)[1] = make_float4(zv[4], zv[5], zv[6], zv[7]);
}

extern "C" void kernel_launch(void* const* d_in, const int* in_sizes, int n_in,
                              void* d_out, int out_size)
{
    const float* initial_c = (const float*)d_in[0];
    // d_in[1] = initial_s (unused)
    const float* current_c = (const float*)d_in[2];
    const float* eps       = (const float*)d_in[3];
    const float* W1  = (const float*)d_in[4];
    const float* b1  = (const float*)d_in[5];
    const float* W2  = (const float*)d_in[6];
    const float* b2  = (const float*)d_in[7];
    const float* W3  = (const float*)d_in[8];
    const float* b3  = (const float*)d_in[9];
    const float* Wm  = (const float*)d_in[10];
    const float* bm  = (const float*)d_in[11];
    const float* Wv  = (const float*)d_in[12];
    const float* bv  = (const float*)d_in[13];
    const float* Wd1 = (const float*)d_in[14];
    const float* bd1 = (const float*)d_in[15];
    const float* Wd2 = (const float*)d_in[16];
    const float* bd2 = (const float*)d_in[17];
    float* out = (float*)d_out;

    cudaFuncSetAttribute(vae_kernel, cudaFuncAttributeMaxDynamicSharedMemorySize, SMEM_BYTES);
    vae_kernel<<<BATCH / NTHREADS, NTHREADS, SMEM_BYTES>>>(
        initial_c, current_c, eps,
        W1, b1, W2, b2, W3, b3, Wm, bm, Wv, bv, Wd1, bd1, Wd2, bd2,
        out);
}